// round 7
// baseline (speedup 1.0000x reference)
#include <cuda_runtime.h>
#include <cstdint>

#define BATCH 4
#define CH    64
#define H     256
#define WID   256
#define HW    (H*WID)
#define CHW   (CH*HW)
#define XT    64            // x-tile per block
#define C2ROWS 257          // center rows -1..255 stored at index yc+1

// scratch (allocation-free: __device__ globals)
__device__ float  g_s[BATCH*HW];                   // per-pixel vertical shift s
__device__ float  g_x2[BATCH*CHW];                 // warped image
__device__ float  g_C2[BATCH*CH*C2ROWS*WID];       // conv3x3(x2) at rows -1..255
__device__ float2 g_Wd[CH*9*CH];                   // [c][tap][oc] duplicated (w,w)

// packed fp32x2 FMA (Blackwell FFMA2 — only reachable via PTX)
#define FMA2(d,a,b) asm("fma.rn.f32x2 %0, %1, %2, %3;" : "=l"(d) : "l"(a), "l"(b), "l"(d))

__device__ __forceinline__ float lo32(uint64_t v){ return __uint_as_float((unsigned)(v & 0xffffffffu)); }
__device__ __forceinline__ float hi32(uint64_t v){ return __uint_as_float((unsigned)(v >> 32)); }

// ---------------------------------------------------------------------------
// Kernel W: transpose+duplicate weights [oc][c][tap] -> [c][tap][oc] as (w,w)
// ---------------------------------------------------------------------------
__global__ __launch_bounds__(256) void wt_kernel(const float* __restrict__ Wg) {
    int i = blockIdx.x * 256 + threadIdx.x;
    if (i >= CH*CH*9) return;
    int oc  = i / (CH*9);
    int rem = i - oc*CH*9;
    int c   = rem / 9;
    int tap = rem - c*9;
    float w = Wg[i];
    g_Wd[(c*9 + tap)*CH + oc] = make_float2(w, w);
}

// ---------------------------------------------------------------------------
// Kernel A: per-pixel channel max -> depth -> s, and vertical bilinear warp x2
// ---------------------------------------------------------------------------
__global__ __launch_bounds__(256) void prep_kernel(const float* __restrict__ X) {
    int idx = blockIdx.x * 256 + threadIdx.x;
    if (idx >= BATCH*HW) return;
    int b   = idx / HW;
    int rem = idx - b*HW;
    int y   = rem / WID;
    int x   = rem - y*WID;

    const float* Xpix = X + b*CHW + y*WID + x;
    float m = -1e30f;
    #pragma unroll 8
    for (int c = 0; c < CH; c++) m = fmaxf(m, Xpix[c*HW]);

    float depth = fminf(fmaxf(m, 1.0f), 50.0f);
    float s = 50.0f / (2.0f * depth);          // FOCAL/(downsample*depth)
    g_s[idx] = s;

    float ys = (float)y - s;
    float fy = floorf(ys);
    int   y0 = (int)fy;
    float w1 = ys - fy;
    float w0 = 1.0f - w1;

    bool ok0 = (y0   >= 0) && (y0   < H);
    bool ok1 = (y0+1 >= 0) && (y0+1 < H);
    const float* Xc0 = X + b*CHW + (ok0 ? y0   : 0)*WID + x;
    const float* Xc1 = X + b*CHW + (ok1 ? y0+1 : 0)*WID + x;
    float* X2p = g_x2 + b*CHW + y*WID + x;

    #pragma unroll 4
    for (int c = 0; c < CH; c++) {
        float a  = ok0 ? Xc0[c*HW] : 0.0f;
        float bb = ok1 ? Xc1[c*HW] : 0.0f;
        X2p[c*HW] = w0*a + w1*bb;
    }
}

// ---------------------------------------------------------------------------
// Dual-row FFMA2 3x3 conv. Block: 64 oc x 64 px x 2 rows, 128 threads,
// per-thread 4 oc x 8 px x 2 rows (32 f32x2 accumulators).
// Input staged as packed pair-rows: sP[ky][j] = (row[yA-1+ky], row[yA+ky]).
// FUSED=false: in=g_x2, center rows yA=2*by-1, yA+1; store into g_C2 (idx yc+1).
// FUSED=true : in=X, rows yA=2*by, yA+1; epilogue interp on g_C2 + min.
// ---------------------------------------------------------------------------
template<bool FUSED>
__global__ __launch_bounds__(128) void conv2_kernel(const float* __restrict__ in,
                                                    float* __restrict__ out) {
    __shared__ __align__(16) float2 sW[2][9*CH];     // duplicated weight pairs
    __shared__ __align__(16) float2 sP[2][3][68];    // packed input pair-rows

    const int x0 = blockIdx.x * XT;
    const int b  = blockIdx.z;
    const int t  = threadIdx.x;
    const int yA = FUSED ? 2*(int)blockIdx.y : 2*(int)blockIdx.y - 1;

    const int ocb = (t & 15) * 4;      // out-channel base
    const int pxb = (t >> 4) * 8;      // pixel base within tile

    uint64_t acc[4][8];
    #pragma unroll
    for (int o = 0; o < 4; o++)
        #pragma unroll
        for (int p = 0; p < 8; p++) acc[o][p] = 0ull;

    const float* inb = in + b*CHW;

    // ---- staging (weights + packed pair-rows) for channel c into buffer buf
    auto stage = [&](int buf, int c) {
        const float2* Wc = g_Wd + c*9*CH;
        #pragma unroll
        for (int i = t; i < 9*CH; i += 128) sW[buf][i] = Wc[i];
        const float* Xc = inb + c*HW;
        #pragma unroll 2
        for (int i = t; i < 3*66; i += 128) {
            int r = i / 66, j = i - r*66;
            int col = x0 - 1 + j;
            int rlo = yA - 1 + r;
            int rhi = yA + r;
            float vlo = 0.0f, vhi = 0.0f;
            if (col >= 0 && col < WID) {
                if (rlo >= 0 && rlo < H) vlo = __ldg(Xc + rlo*WID + col);
                if (rhi >= 0 && rhi < H) vhi = __ldg(Xc + rhi*WID + col);
            }
            sP[buf][r][j] = make_float2(vlo, vhi);
        }
    };

    stage(0, 0);
    __syncthreads();
    int buf = 0;

    for (int c = 0; c < CH; c++) {
        if (c + 1 < CH) stage(buf ^ 1, c + 1);

        #pragma unroll
        for (int ky = 0; ky < 3; ky++) {
            uint64_t rj[10];
            const ulonglong2* rp = (const ulonglong2*)&sP[buf][ky][pxb];
            #pragma unroll
            for (int j = 0; j < 5; j++) {
                ulonglong2 q = rp[j];
                rj[2*j]   = q.x;
                rj[2*j+1] = q.y;
            }
            #pragma unroll
            for (int kx = 0; kx < 3; kx++) {
                const ulonglong2* wp = (const ulonglong2*)&sW[buf][(ky*3+kx)*CH + ocb];
                ulonglong2 wq0 = wp[0];
                ulonglong2 wq1 = wp[1];
                uint64_t w[4] = {wq0.x, wq0.y, wq1.x, wq1.y};
                #pragma unroll
                for (int o = 0; o < 4; o++) {
                    #pragma unroll
                    for (int p = 0; p < 8; p++) FMA2(acc[o][p], w[o], rj[p + kx]);
                }
            }
        }
        __syncthreads();
        buf ^= 1;
    }

    const int x = x0 + pxb;

    if (!FUSED) {
        // lo lanes = center row yA (idx yA+1), hi lanes = row yA+1 (idx yA+2)
        const int idxLo = yA + 1;                 // always in [0,256]
        const bool hiOk = (yA + 1) <= (H - 1);    // center row yA+1 valid?
        #pragma unroll
        for (int o = 0; o < 4; o++) {
            float* base = g_C2 + ((long)(b*CH + ocb + o))*C2ROWS*WID + x;
            float4 v0 = make_float4(lo32(acc[o][0]), lo32(acc[o][1]), lo32(acc[o][2]), lo32(acc[o][3]));
            float4 v1 = make_float4(lo32(acc[o][4]), lo32(acc[o][5]), lo32(acc[o][6]), lo32(acc[o][7]));
            *(float4*)(base + (long)idxLo*WID)     = v0;
            *(float4*)(base + (long)idxLo*WID + 4) = v1;
            if (hiOk) {
                float4 h0 = make_float4(hi32(acc[o][0]), hi32(acc[o][1]), hi32(acc[o][2]), hi32(acc[o][3]));
                float4 h1 = make_float4(hi32(acc[o][4]), hi32(acc[o][5]), hi32(acc[o][6]), hi32(acc[o][7]));
                *(float4*)(base + (long)(idxLo+1)*WID)     = h0;
                *(float4*)(base + (long)(idxLo+1)*WID + 4) = h1;
            }
        }
    } else {
        // interp params for rows yA (lo) and yA+1 (hi), 8 pixels each
        int   y0A[8], y0B[8];
        float w0A[8], w1A[8], w0B[8], w1B[8];
        #pragma unroll
        for (int p = 0; p < 8; p++) {
            float sA = g_s[b*HW + yA*WID + x + p];
            float ysA = (float)yA - sA;
            float fA = floorf(ysA);
            y0A[p] = (int)fA;  w1A[p] = ysA - fA;  w0A[p] = 1.0f - w1A[p];

            float sB = g_s[b*HW + (yA+1)*WID + x + p];
            float ysB = (float)(yA+1) - sB;
            float fB = floorf(ysB);
            y0B[p] = (int)fB;  w1B[p] = ysB - fB;  w0B[p] = 1.0f - w1B[p];
        }
        #pragma unroll
        for (int o = 0; o < 4; o++) {
            const float* cc = g_C2 + ((long)(b*CH + ocb + o))*C2ROWS*WID + x;
            float rA[8], rB[8];
            #pragma unroll
            for (int p = 0; p < 8; p++) {
                int ya = y0A[p];
                float A0 = (ya >= -1) ? cc[(ya+1)*WID + p] : 0.0f;
                float A1 = (ya >= -2) ? cc[(ya+2)*WID + p] : 0.0f;
                rA[p] = fminf(lo32(acc[o][p]), w0A[p]*A0 + w1A[p]*A1);

                int yb = y0B[p];
                float B0 = (yb >= -1) ? cc[(yb+1)*WID + p] : 0.0f;
                float B1 = (yb >= -2) ? cc[(yb+2)*WID + p] : 0.0f;
                rB[p] = fminf(hi32(acc[o][p]), w0B[p]*B0 + w1B[p]*B1);
            }
            float* op = out + (((long)(b*CH + ocb + o))*H + yA)*WID + x;
            *(float4*)(op)           = make_float4(rA[0], rA[1], rA[2], rA[3]);
            *(float4*)(op + 4)       = make_float4(rA[4], rA[5], rA[6], rA[7]);
            *(float4*)(op + WID)     = make_float4(rB[0], rB[1], rB[2], rB[3]);
            *(float4*)(op + WID + 4) = make_float4(rB[4], rB[5], rB[6], rB[7]);
        }
    }
}

// ---------------------------------------------------------------------------
extern "C" void kernel_launch(void* const* d_in, const int* in_sizes, int n_in,
                              void* d_out, int out_size) {
    const float* X  = (const float*)d_in[0];   // [4,64,256,256]
    const float* Wg = (const float*)d_in[1];   // [64,64,3,3]
    float* Out = (float*)d_out;                // [4,64,256,256]

    wt_kernel<<<(CH*CH*9 + 255)/256, 256>>>(Wg);
    prep_kernel<<<(BATCH*HW + 255)/256, 256>>>(X);

    // C2 = conv3x3(x2) at center rows -1..255 (129 row-pairs, last hi masked)
    {
        float* x2p;  cudaGetSymbolAddress((void**)&x2p, g_x2);
        dim3 grid(WID/XT, 129, BATCH);
        conv2_kernel<false><<<grid, 128>>>(x2p, nullptr);
    }
    // upper conv on X + fused interp/min epilogue (128 row-pairs)
    {
        dim3 grid(WID/XT, H/2, BATCH);
        conv2_kernel<true><<<grid, 128>>>(X, Out);
    }
}